// round 11
// baseline (speedup 1.0000x reference)
#include <cuda_runtime.h>
#include <math.h>
#include <stdint.h>

#define BATCH 256
#define NSTEP 128
#define MSZ   512
#define SLOTS 15
#define SSZ   16

__device__ float g_qproj[(size_t)BATCH * NSTEP * MSZ];
__device__ float g_gproj[BATCH * MSZ];
__device__ float g_memproj[BATCH * SLOTS * MSZ];

// ---------------------------------------------------------------------------
__device__ __forceinline__ float f2tf(float x) {
    uint32_t r;
    asm("cvt.rna.tf32.f32 %0, %1;" : "=r"(r) : "f"(x));
    return __uint_as_float(r);
}
__device__ __forceinline__ void mma_tf32(float c[4],
                                         uint32_t a0, uint32_t a1,
                                         uint32_t a2, uint32_t a3,
                                         uint32_t b0, uint32_t b1) {
    asm volatile(
        "mma.sync.aligned.m16n8k8.row.col.f32.tf32.tf32.f32 "
        "{%0,%1,%2,%3}, {%4,%5,%6,%7}, {%8,%9}, {%0,%1,%2,%3};"
        : "+f"(c[0]), "+f"(c[1]), "+f"(c[2]), "+f"(c[3])
        : "r"(a0), "r"(a1), "r"(a2), "r"(a3), "r"(b0), "r"(b1));
}

// ---------------------------------------------------------------------------
// Split-TF32 GEMM, 512 threads (16 warps, 4x4 grid, 32x32 warp tiles) for
// 4 warps/SMSP occupancy. Same math/order as the proven 256-thr version.
// grid (4, 288): y<256 qproj, y<258 gproj(+bias), else memproj.
// ---------------------------------------------------------------------------
#define ASTR 72

__global__ __launch_bounds__(512) void tf32_gemm_all(
    const float* __restrict__ states, const float* __restrict__ gt,
    const float* __restrict__ his_mem, const float* __restrict__ W,
    const float* __restrict__ bias, float* __restrict__ qproj,
    float* __restrict__ gproj, float* __restrict__ memproj)
{
    __shared__ float sA[128 * ASTR];
    __shared__ float sB[128 * ASTR];

    int y = blockIdx.y;
    const float *X, *Wb, *addp = nullptr;
    float* outp;
    int r0;
    if (y < 256)      { X = states;  r0 = y * 128;         Wb = W;        outp = qproj; }
    else if (y < 258) { X = gt;      r0 = (y - 256) * 128; Wb = W + 512;  outp = gproj; addp = bias; }
    else              { X = his_mem; r0 = (y - 258) * 128; Wb = W + 1024; outp = memproj; }

    int tid  = threadIdx.x;
    int warp = tid >> 5, lane = tid & 31;
    int g    = lane >> 2, tig = lane & 3;
    int wm   = (warp >> 2) * 32;
    int wn   = (warp & 3) * 32;
    int n0   = blockIdx.x * 128;

    float acc[2][4][4];
#pragma unroll
    for (int a = 0; a < 2; a++)
#pragma unroll
        for (int b = 0; b < 4; b++)
#pragma unroll
            for (int c = 0; c < 4; c++) acc[a][b][c] = 0.f;

    int lr = tid >> 2;          // 0..127
    int kc = (tid & 3) * 8;     // 0,8,16,24

    const float* Aptr = X  + (size_t)(r0 + lr) * 512  + kc;
    const float* Bptr = Wb + (size_t)(n0 + lr) * 1536 + kc;

    float4 pa0 = *(const float4*)Aptr, pa1 = *(const float4*)(Aptr + 4);
    float4 pb0 = *(const float4*)Bptr, pb1 = *(const float4*)(Bptr + 4);

    for (int t = 0; t < 16; t++) {
        __syncthreads();
        {
            float* dA = &sA[lr * ASTR + 2 * kc];
            float* dB = &sB[lr * ASTR + 2 * kc];
            float4 v = pa0;
            float h0 = f2tf(v.x), h1 = f2tf(v.y), h2 = f2tf(v.z), h3 = f2tf(v.w);
            *(float4*)(dA)     = make_float4(h0, f2tf(v.x - h0), h1, f2tf(v.y - h1));
            *(float4*)(dA + 4) = make_float4(h2, f2tf(v.z - h2), h3, f2tf(v.w - h3));
            v = pa1;
            h0 = f2tf(v.x); h1 = f2tf(v.y); h2 = f2tf(v.z); h3 = f2tf(v.w);
            *(float4*)(dA + 8)  = make_float4(h0, f2tf(v.x - h0), h1, f2tf(v.y - h1));
            *(float4*)(dA + 12) = make_float4(h2, f2tf(v.z - h2), h3, f2tf(v.w - h3));
            v = pb0;
            h0 = f2tf(v.x); h1 = f2tf(v.y); h2 = f2tf(v.z); h3 = f2tf(v.w);
            *(float4*)(dB)     = make_float4(h0, f2tf(v.x - h0), h1, f2tf(v.y - h1));
            *(float4*)(dB + 4) = make_float4(h2, f2tf(v.z - h2), h3, f2tf(v.w - h3));
            v = pb1;
            h0 = f2tf(v.x); h1 = f2tf(v.y); h2 = f2tf(v.z); h3 = f2tf(v.w);
            *(float4*)(dB + 8)  = make_float4(h0, f2tf(v.x - h0), h1, f2tf(v.y - h1));
            *(float4*)(dB + 12) = make_float4(h2, f2tf(v.z - h2), h3, f2tf(v.w - h3));
        }
        __syncthreads();

        if (t + 1 < 16) {
            int k0 = (t + 1) * 32;
            pa0 = *(const float4*)(Aptr + k0);
            pa1 = *(const float4*)(Aptr + k0 + 4);
            pb0 = *(const float4*)(Bptr + k0);
            pb1 = *(const float4*)(Bptr + k0 + 4);
        }

#pragma unroll
        for (int k8 = 0; k8 < 4; k8++) {
            uint32_t Ah[2][4], Al[2][4], Bh[4][2], Bl[4][2];
#pragma unroll
            for (int mf = 0; mf < 2; mf++) {
                int m0 = wm + mf * 16;
                float2 v0 = *(float2*)&sA[(m0 + g)     * ASTR + (k8 * 8 + tig)     * 2];
                float2 v1 = *(float2*)&sA[(m0 + g + 8) * ASTR + (k8 * 8 + tig)     * 2];
                float2 v2 = *(float2*)&sA[(m0 + g)     * ASTR + (k8 * 8 + tig + 4) * 2];
                float2 v3 = *(float2*)&sA[(m0 + g + 8) * ASTR + (k8 * 8 + tig + 4) * 2];
                Ah[mf][0] = __float_as_uint(v0.x); Al[mf][0] = __float_as_uint(v0.y);
                Ah[mf][1] = __float_as_uint(v1.x); Al[mf][1] = __float_as_uint(v1.y);
                Ah[mf][2] = __float_as_uint(v2.x); Al[mf][2] = __float_as_uint(v2.y);
                Ah[mf][3] = __float_as_uint(v3.x); Al[mf][3] = __float_as_uint(v3.y);
            }
#pragma unroll
            for (int nf = 0; nf < 4; nf++) {
                int n = wn + nf * 8 + g;
                float2 v0 = *(float2*)&sB[n * ASTR + (k8 * 8 + tig)     * 2];
                float2 v1 = *(float2*)&sB[n * ASTR + (k8 * 8 + tig + 4) * 2];
                Bh[nf][0] = __float_as_uint(v0.x); Bl[nf][0] = __float_as_uint(v0.y);
                Bh[nf][1] = __float_as_uint(v1.x); Bl[nf][1] = __float_as_uint(v1.y);
            }
#pragma unroll
            for (int mf = 0; mf < 2; mf++)
#pragma unroll
                for (int nf = 0; nf < 4; nf++) {
                    mma_tf32(acc[mf][nf], Ah[mf][0], Ah[mf][1], Ah[mf][2], Ah[mf][3],
                             Bh[nf][0], Bh[nf][1]);
                    mma_tf32(acc[mf][nf], Ah[mf][0], Ah[mf][1], Ah[mf][2], Ah[mf][3],
                             Bl[nf][0], Bl[nf][1]);
                    mma_tf32(acc[mf][nf], Al[mf][0], Al[mf][1], Al[mf][2], Al[mf][3],
                             Bh[nf][0], Bh[nf][1]);
                }
        }
    }

#pragma unroll
    for (int mf = 0; mf < 2; mf++)
#pragma unroll
        for (int nf = 0; nf < 4; nf++) {
            int col_l = wn + nf * 8 + 2 * tig;
            int col   = n0 + col_l;
            int row   = r0 + wm + mf * 16 + g;
            float a0 = 0.f, a1 = 0.f;
            if (addp) { a0 = addp[col]; a1 = addp[col + 1]; }
            float2 s0 = {acc[mf][nf][0] + a0, acc[mf][nf][1] + a1};
            float2 s1 = {acc[mf][nf][2] + a0, acc[mf][nf][3] + a1};
            *(float2*)&outp[(size_t)row * MSZ + col]       = s0;
            *(float2*)&outp[(size_t)(row + 8) * MSZ + col] = s1;
        }
}

// ---------------------------------------------------------------------------
__device__ __forceinline__ float tanh_acc(float x) {
    float e;
    asm("ex2.approx.f32 %0, %1;" : "=f"(e) : "f"(x * 2.88539008177793f));
    float r;
    asm("rcp.approx.f32 %0, %1;" : "=f"(r) : "f"(e + 1.0f));
    return fmaf(-2.0f, r, 1.0f);
}

__device__ __forceinline__ int decide(float e, float gn, int lane) {
    float mx = e;
#pragma unroll
    for (int off = 8; off > 0; off >>= 1)
        mx = fmaxf(mx, __shfl_xor_sync(0xffffffffu, mx, off));
    float ex = expf(e - mx);
    float sm = ex;
#pragma unroll
    for (int off = 8; off > 0; off >>= 1)
        sm += __shfl_xor_sync(0xffffffffu, sm, off);
    float w = ex / sm;
    if (lane == 15) w += 10.0f;
    float z = (lane < 16) ? (w + gn) : -1e30f;
    float bz = z; int bi = lane;
#pragma unroll
    for (int off = 8; off > 0; off >>= 1) {
        float oz = __shfl_xor_sync(0xffffffffu, bz, off);
        int   oi = __shfl_xor_sync(0xffffffffu, bi, off);
        if (oz > bz || (oz == bz && oi < bi)) { bz = oz; bi = oi; }
    }
    return __shfl_sync(0xffffffffu, bi, 0);
}

// ---------------------------------------------------------------------------
// writer3: fused. Phase E0 (barrier-free, warp s sweeps all steps for its
// slot vs initial memproj) -> one sync -> parallel decisions -> rare replay.
// ---------------------------------------------------------------------------
__global__ __launch_bounds__(512) void writer3(
    const float* __restrict__ his_mem, const float* __restrict__ states,
    const float* __restrict__ states_mask, const float* __restrict__ gumbel_u,
    const float* __restrict__ attn_W, const float* __restrict__ v,
    const float* __restrict__ qproj, const float* __restrict__ gproj,
    const float* __restrict__ memproj,
    float* __restrict__ out_hm, float* __restrict__ out_log)
{
    __shared__ float s_E0[NSTEP][SSZ];
    __shared__ float s_g[NSTEP][SSZ];
    __shared__ float s_mask[NSTEP];
    __shared__ int   s_dec[NSTEP];
    __shared__ float s_e[SSZ];
    __shared__ int   s_dirty[SSZ];
    __shared__ float s_q[MSZ];
    __shared__ float s_row[MSZ];
    __shared__ int   s_lastwrite[SLOTS];
    __shared__ int   s_t0;

    int b = blockIdx.x, tid = threadIdx.x, lane = tid & 31, warp = tid >> 5;

    if (tid < SLOTS) s_lastwrite[tid] = -1;
    if (tid < SSZ)   s_dirty[tid] = 0;
    if (tid == 0)    s_t0 = NSTEP;
    if (tid < NSTEP) s_mask[tid] = states_mask[b * NSTEP + tid];
    {
        float4 u4 = *(const float4*)(gumbel_u + (size_t)b * NSTEP * SSZ + tid * 4);
        float uu[4] = {u4.x, u4.y, u4.z, u4.w}, gg[4];
#pragma unroll
        for (int i = 0; i < 4; i++) {
            float u = fminf(fmaxf(uu[i], 1e-20f), 1.0f);
            gg[i] = -logf(-logf(u) + 1e-20f);
        }
        *(float4*)(&s_g[0][0] + tid * 4) = make_float4(gg[0], gg[1], gg[2], gg[3]);
    }

    float vreg[16], mp[16], ga[16];
#pragma unroll
    for (int i = 0; i < 16; i++) {
        int m = lane + 32 * i;
        vreg[i] = v[m];
        ga[i]   = gproj[b * MSZ + m];
        mp[i]   = (warp < SLOTS) ? memproj[((size_t)b * SLOTS + warp) * MSZ + m] : 0.f;
    }

    // Phase E0: barrier-free; warp w computes slot w energies for all steps.
    {
        const float* q = qproj + (size_t)b * NSTEP * MSZ;
        for (int t = 0; t < NSTEP; t++) {
            float p = 0.f;
#pragma unroll
            for (int i = 0; i < 16; i++) {
                float qq = __ldg(q + t * MSZ + lane + 32 * i);
                p += tanh_acc((qq + ga[i]) + mp[i]) * vreg[i];
            }
#pragma unroll
            for (int off = 16; off > 0; off >>= 1)
                p += __shfl_xor_sync(0xffffffffu, p, off);
            if (lane == 0) s_E0[t][warp] = p;
        }
    }
    __syncthreads();

    // Phase 1: parallel decisions (warp w -> steps 8w..8w+7)
    for (int j = 0; j < 8; j++) {
        int t = warp * 8 + j;
        float e = (lane < 16) ? s_E0[t][lane] : -1e30f;
        int bi = decide(e, (lane < 16) ? s_g[t][lane] : 0.f, lane);
        if (lane == 0) {
            s_dec[t] = bi;
            if (bi < SLOTS && s_mask[t] != 0.f) atomicMin(&s_t0, t);
        }
    }
    __syncthreads();

    int t0 = s_t0;
    int tmax = (t0 < NSTEP) ? t0 : NSTEP - 1;
    for (int idx = tid; idx < (tmax + 1) * SSZ; idx += 512) {
        int t = idx >> 4, s = idx & 15;
        out_log[((size_t)b * NSTEP + t) * SSZ + s] = (s == s_dec[t]) ? 1.f : 0.f;
    }

    if (t0 < NSTEP) {
        float gadd = gproj[b * MSZ + tid];
        int k = s_dec[t0];
        for (int t = t0; t < NSTEP; t++) {
            if (k >= 0) {       // write event: slot k takes states[b,t]
                s_q[tid] = states[((size_t)b * NSTEP + t) * MSZ + tid];
                if (tid == 0) { s_lastwrite[k] = t; s_dirty[k] = 1; }
                __syncthreads();
                float acc = 0.f;
                const float4* w4  = (const float4*)(attn_W + (size_t)tid * 1536 + 1024);
                const float4* st4 = (const float4*)s_q;
                for (int kk = 0; kk < MSZ / 4; kk++) {
                    float4 ww = w4[kk]; float4 s2 = st4[kk];
                    acc += ww.x * s2.x + ww.y * s2.y + ww.z * s2.z + ww.w * s2.w;
                }
                s_row[tid] = acc;
                __syncthreads();
                if (warp == k) {
#pragma unroll
                    for (int i = 0; i < 16; i++) mp[i] = s_row[lane + 32 * i];
                }
            }
            if (t + 1 >= NSTEP) break;

            int tn = t + 1;
            s_q[tid] = qproj[((size_t)b * NSTEP + tn) * MSZ + tid] + gadd;
            __syncthreads();
            if (s_dirty[warp]) {
                float p = 0.f;
#pragma unroll
                for (int i = 0; i < 16; i++) {
                    int m = lane + 32 * i;
                    p += tanh_acc(s_q[m] + mp[i]) * vreg[i];
                }
#pragma unroll
                for (int off = 16; off > 0; off >>= 1)
                    p += __shfl_xor_sync(0xffffffffu, p, off);
                if (lane == 0) s_e[warp] = p;
            }
            __syncthreads();

            float e = (lane < 16)
                    ? (s_dirty[lane] ? s_e[lane] : s_E0[tn][lane]) : -1e30f;
            int bi = decide(e, (lane < 16) ? s_g[tn][lane] : 0.f, lane);
            if (warp == 0 && lane < 16)
                out_log[((size_t)b * NSTEP + tn) * SSZ + lane] = (lane == bi) ? 1.f : 0.f;
            k = (bi < SLOTS && s_mask[tn] != 0.f) ? bi : -1;
            __syncthreads();
        }
        __syncthreads();
    }

    for (int s = 0; s < SLOTS; s++) {
        int lw = s_lastwrite[s];
        const float* src = (lw >= 0)
            ? (states + ((size_t)b * NSTEP + lw) * MSZ)
            : (his_mem + ((size_t)b * SLOTS + s) * MSZ);
        out_hm[((size_t)b * SLOTS + s) * MSZ + tid] = src[tid];
    }
}

// ---------------------------------------------------------------------------
extern "C" void kernel_launch(void* const* d_in, const int* in_sizes, int n_in,
                              void* d_out, int out_size)
{
    const float* his_mem     = (const float*)d_in[0];
    const float* states      = (const float*)d_in[1];
    const float* states_mask = (const float*)d_in[2];
    const float* gt          = (const float*)d_in[3];
    const float* gumbel_u    = (const float*)d_in[5];
    const float* attn_W      = (const float*)d_in[6];
    const float* attn_b      = (const float*)d_in[7];
    const float* v           = (const float*)d_in[8];

    float* out     = (float*)d_out;
    float* out_hm  = out;
    float* out_log = out + (size_t)BATCH * SLOTS * MSZ;

    float *qproj = nullptr, *gproj = nullptr, *memproj = nullptr;
    cudaGetSymbolAddress((void**)&qproj, g_qproj);
    cudaGetSymbolAddress((void**)&gproj, g_gproj);
    cudaGetSymbolAddress((void**)&memproj, g_memproj);

    dim3 grid(MSZ / 128, 256 + 2 + 30);
    tf32_gemm_all<<<grid, 512>>>(states, gt, his_mem, attn_W, attn_b,
                                 qproj, gproj, memproj);

    writer3<<<BATCH, 512>>>(his_mem, states, states_mask, gumbel_u,
                            attn_W, v, qproj, gproj, memproj,
                            out_hm, out_log);
}

// round 12
// speedup vs baseline: 1.8853x; 1.8853x over previous
#include <cuda_runtime.h>
#include <math.h>
#include <stdint.h>

#define BATCH 256
#define NSTEP 128
#define MSZ   512
#define SLOTS 15
#define SSZ   16

__device__ float g_qproj[(size_t)BATCH * NSTEP * MSZ];
__device__ float g_gproj[BATCH * MSZ];
__device__ float g_memproj[BATCH * SLOTS * MSZ];

// ---------------------------------------------------------------------------
__device__ __forceinline__ float f2tf(float x) {
    uint32_t r;
    asm("cvt.rna.tf32.f32 %0, %1;" : "=r"(r) : "f"(x));
    return __uint_as_float(r);
}
__device__ __forceinline__ void mma_tf32(float c[4],
                                         uint32_t a0, uint32_t a1,
                                         uint32_t a2, uint32_t a3,
                                         uint32_t b0, uint32_t b1) {
    asm volatile(
        "mma.sync.aligned.m16n8k8.row.col.f32.tf32.tf32.f32 "
        "{%0,%1,%2,%3}, {%4,%5,%6,%7}, {%8,%9}, {%0,%1,%2,%3};"
        : "+f"(c[0]), "+f"(c[1]), "+f"(c[2]), "+f"(c[3])
        : "r"(a0), "r"(a1), "r"(a2), "r"(a3), "r"(b0), "r"(b1));
}

// ---------------------------------------------------------------------------
// Split-TF32 GEMM, register-lean for 2 CTAs/SM (4 warps/SMSP).
// BM=64, BN=128, BK=32, 256 threads, warp grid 2(m) x 4(n), warp tile 32x32.
// No register prefetch: co-resident CTA hides load latency.
// grid (4, 576): y<512 qproj, y<516 gproj(+bias), else memproj.
// ---------------------------------------------------------------------------
#define ASTR 72

__global__ __launch_bounds__(256, 2) void tf32_gemm_all(
    const float* __restrict__ states, const float* __restrict__ gt,
    const float* __restrict__ his_mem, const float* __restrict__ W,
    const float* __restrict__ bias, float* __restrict__ qproj,
    float* __restrict__ gproj, float* __restrict__ memproj)
{
    __shared__ float sA[64 * ASTR];
    __shared__ float sB[128 * ASTR];

    int y = blockIdx.y;
    const float *X, *Wb, *addp = nullptr;
    float* outp;
    int r0;
    if (y < 512)      { X = states;  r0 = y * 64;         Wb = W;        outp = qproj; }
    else if (y < 516) { X = gt;      r0 = (y - 512) * 64; Wb = W + 512;  outp = gproj; addp = bias; }
    else              { X = his_mem; r0 = (y - 516) * 64; Wb = W + 1024; outp = memproj; }

    int tid  = threadIdx.x;
    int warp = tid >> 5, lane = tid & 31;
    int g    = lane >> 2, tig = lane & 3;
    int wm   = (warp >> 2) * 32;   // {0, 32}
    int wn   = (warp & 3) * 32;    // {0,32,64,96}
    int n0   = blockIdx.x * 128;

    float acc[2][4][4];
#pragma unroll
    for (int a = 0; a < 2; a++)
#pragma unroll
        for (int b = 0; b < 4; b++)
#pragma unroll
            for (int c = 0; c < 4; c++) acc[a][b][c] = 0.f;

    // A tile: 64 rows x 32 k -> 8 floats/thread
    int lrA = tid >> 2;          // 0..63
    int kcA = (tid & 3) * 8;     // 0,8,16,24
    // B tile: 128 rows x 32 k -> 16 floats/thread
    int lrB = tid >> 1;          // 0..127
    int kcB = (tid & 1) * 16;    // 0,16

    const float* Aptr = X  + (size_t)(r0 + lrA) * 512  + kcA;
    const float* Bptr = Wb + (size_t)(n0 + lrB) * 1536 + kcB;

    for (int t = 0; t < 16; t++) {
        int k0 = t * 32;
        float4 a0 = *(const float4*)(Aptr + k0);
        float4 a1 = *(const float4*)(Aptr + k0 + 4);
        float4 b0 = *(const float4*)(Bptr + k0);
        float4 b1 = *(const float4*)(Bptr + k0 + 4);
        float4 b2 = *(const float4*)(Bptr + k0 + 8);
        float4 b3 = *(const float4*)(Bptr + k0 + 12);
        __syncthreads();
        {
            float* dA = &sA[lrA * ASTR + 2 * kcA];
            float h0 = f2tf(a0.x), h1 = f2tf(a0.y), h2 = f2tf(a0.z), h3 = f2tf(a0.w);
            *(float4*)(dA)     = make_float4(h0, f2tf(a0.x - h0), h1, f2tf(a0.y - h1));
            *(float4*)(dA + 4) = make_float4(h2, f2tf(a0.z - h2), h3, f2tf(a0.w - h3));
            h0 = f2tf(a1.x); h1 = f2tf(a1.y); h2 = f2tf(a1.z); h3 = f2tf(a1.w);
            *(float4*)(dA + 8)  = make_float4(h0, f2tf(a1.x - h0), h1, f2tf(a1.y - h1));
            *(float4*)(dA + 12) = make_float4(h2, f2tf(a1.z - h2), h3, f2tf(a1.w - h3));

            float* dB = &sB[lrB * ASTR + 2 * kcB];
            h0 = f2tf(b0.x); h1 = f2tf(b0.y); h2 = f2tf(b0.z); h3 = f2tf(b0.w);
            *(float4*)(dB)     = make_float4(h0, f2tf(b0.x - h0), h1, f2tf(b0.y - h1));
            *(float4*)(dB + 4) = make_float4(h2, f2tf(b0.z - h2), h3, f2tf(b0.w - h3));
            h0 = f2tf(b1.x); h1 = f2tf(b1.y); h2 = f2tf(b1.z); h3 = f2tf(b1.w);
            *(float4*)(dB + 8)  = make_float4(h0, f2tf(b1.x - h0), h1, f2tf(b1.y - h1));
            *(float4*)(dB + 12) = make_float4(h2, f2tf(b1.z - h2), h3, f2tf(b1.w - h3));
            h0 = f2tf(b2.x); h1 = f2tf(b2.y); h2 = f2tf(b2.z); h3 = f2tf(b2.w);
            *(float4*)(dB + 16) = make_float4(h0, f2tf(b2.x - h0), h1, f2tf(b2.y - h1));
            *(float4*)(dB + 20) = make_float4(h2, f2tf(b2.z - h2), h3, f2tf(b2.w - h3));
            h0 = f2tf(b3.x); h1 = f2tf(b3.y); h2 = f2tf(b3.z); h3 = f2tf(b3.w);
            *(float4*)(dB + 24) = make_float4(h0, f2tf(b3.x - h0), h1, f2tf(b3.y - h1));
            *(float4*)(dB + 28) = make_float4(h2, f2tf(b3.z - h2), h3, f2tf(b3.w - h3));
        }
        __syncthreads();

#pragma unroll
        for (int k8 = 0; k8 < 4; k8++) {
            uint32_t Ah[2][4], Al[2][4], Bh[4][2], Bl[4][2];
#pragma unroll
            for (int mf = 0; mf < 2; mf++) {
                int m0 = wm + mf * 16;
                float2 v0 = *(float2*)&sA[(m0 + g)     * ASTR + (k8 * 8 + tig)     * 2];
                float2 v1 = *(float2*)&sA[(m0 + g + 8) * ASTR + (k8 * 8 + tig)     * 2];
                float2 v2 = *(float2*)&sA[(m0 + g)     * ASTR + (k8 * 8 + tig + 4) * 2];
                float2 v3 = *(float2*)&sA[(m0 + g + 8) * ASTR + (k8 * 8 + tig + 4) * 2];
                Ah[mf][0] = __float_as_uint(v0.x); Al[mf][0] = __float_as_uint(v0.y);
                Ah[mf][1] = __float_as_uint(v1.x); Al[mf][1] = __float_as_uint(v1.y);
                Ah[mf][2] = __float_as_uint(v2.x); Al[mf][2] = __float_as_uint(v2.y);
                Ah[mf][3] = __float_as_uint(v3.x); Al[mf][3] = __float_as_uint(v3.y);
            }
#pragma unroll
            for (int nf = 0; nf < 4; nf++) {
                int n = wn + nf * 8 + g;
                float2 v0 = *(float2*)&sB[n * ASTR + (k8 * 8 + tig)     * 2];
                float2 v1 = *(float2*)&sB[n * ASTR + (k8 * 8 + tig + 4) * 2];
                Bh[nf][0] = __float_as_uint(v0.x); Bl[nf][0] = __float_as_uint(v0.y);
                Bh[nf][1] = __float_as_uint(v1.x); Bl[nf][1] = __float_as_uint(v1.y);
            }
#pragma unroll
            for (int mf = 0; mf < 2; mf++)
#pragma unroll
                for (int nf = 0; nf < 4; nf++) {
                    mma_tf32(acc[mf][nf], Ah[mf][0], Ah[mf][1], Ah[mf][2], Ah[mf][3],
                             Bh[nf][0], Bh[nf][1]);
                    mma_tf32(acc[mf][nf], Ah[mf][0], Ah[mf][1], Ah[mf][2], Ah[mf][3],
                             Bl[nf][0], Bl[nf][1]);
                    mma_tf32(acc[mf][nf], Al[mf][0], Al[mf][1], Al[mf][2], Al[mf][3],
                             Bh[nf][0], Bh[nf][1]);
                }
        }
    }

#pragma unroll
    for (int mf = 0; mf < 2; mf++)
#pragma unroll
        for (int nf = 0; nf < 4; nf++) {
            int col_l = wn + nf * 8 + 2 * tig;
            int col   = n0 + col_l;
            int row   = r0 + wm + mf * 16 + g;
            float a0 = 0.f, a1 = 0.f;
            if (addp) { a0 = addp[col]; a1 = addp[col + 1]; }
            float2 s0 = {acc[mf][nf][0] + a0, acc[mf][nf][1] + a1};
            float2 s1 = {acc[mf][nf][2] + a0, acc[mf][nf][3] + a1};
            *(float2*)&outp[(size_t)row * MSZ + col]       = s0;
            *(float2*)&outp[(size_t)(row + 8) * MSZ + col] = s1;
        }
}

// ---------------------------------------------------------------------------
__device__ __forceinline__ float tanh_acc(float x) {
    float e;
    asm("ex2.approx.f32 %0, %1;" : "=f"(e) : "f"(x * 2.88539008177793f));
    float r;
    asm("rcp.approx.f32 %0, %1;" : "=f"(r) : "f"(e + 1.0f));
    return fmaf(-2.0f, r, 1.0f);
}

// ---------------------------------------------------------------------------
// Sequential writer — proven R6 version, verbatim.
// ---------------------------------------------------------------------------
__global__ __launch_bounds__(512, 2) void writer_kernel(
    const float* __restrict__ his_mem, const float* __restrict__ states,
    const float* __restrict__ states_mask, const float* __restrict__ gumbel_u,
    const float* __restrict__ attn_W, const float* __restrict__ v,
    const float* __restrict__ qproj, const float* __restrict__ gproj,
    const float* __restrict__ memproj,
    float* __restrict__ out_hm, float* __restrict__ out_log)
{
    __shared__ float s_q[2][MSZ];
    __shared__ float s_v[MSZ];
    __shared__ float s_g[NSTEP][SSZ];
    __shared__ float s_mask[NSTEP];
    __shared__ float s_e[SSZ];
    __shared__ float s_tmp[MSZ];
    __shared__ float s_row[MSZ];
    __shared__ int   s_lastwrite[SLOTS];

    int b = blockIdx.x, tid = threadIdx.x, lane = tid & 31, warp = tid >> 5;

    s_v[tid] = v[tid];
    if (tid < SLOTS) s_lastwrite[tid] = -1;
    if (tid < NSTEP) s_mask[tid] = states_mask[b * NSTEP + tid];
    {
        float4 u4 = *(const float4*)(gumbel_u + (size_t)b * NSTEP * SSZ + tid * 4);
        float uu[4] = {u4.x, u4.y, u4.z, u4.w}, gg[4];
#pragma unroll
        for (int i = 0; i < 4; i++) {
            float u = fminf(fmaxf(uu[i], 1e-20f), 1.0f);
            gg[i] = -logf(-logf(u) + 1e-20f);
        }
        *(float4*)(&s_g[0][0] + tid * 4) = make_float4(gg[0], gg[1], gg[2], gg[3]);
    }

    float gadd = gproj[b * MSZ + tid];
    float mp[16];
#pragma unroll
    for (int i = 0; i < 16; i++)
        mp[i] = (warp < SLOTS)
              ? memproj[((size_t)b * SLOTS + warp) * MSZ + lane + 32 * i] : 0.f;

    const float* qrow = qproj + (size_t)b * NSTEP * MSZ;
    s_q[0][tid] = qrow[tid] + gadd;
    __syncthreads();

    for (int t = 0; t < NSTEP; t++) {
        int cur = t & 1;
        float qn = 0.f;
        if (t + 1 < NSTEP) qn = qrow[(t + 1) * MSZ + tid];

        float p = 0.f;
#pragma unroll
        for (int i = 0; i < 16; i++) {
            int m = lane + 32 * i;
            p += tanh_acc(s_q[cur][m] + mp[i]) * s_v[m];
        }
#pragma unroll
        for (int off = 16; off > 0; off >>= 1)
            p += __shfl_xor_sync(0xffffffffu, p, off);
        if (lane == 0) s_e[warp] = p;
        __syncthreads();

        float e = (lane < 16) ? s_e[lane] : -1e30f;
        float mx = e;
#pragma unroll
        for (int off = 8; off > 0; off >>= 1)
            mx = fmaxf(mx, __shfl_xor_sync(0xffffffffu, mx, off));
        float ex = expf(e - mx);
        float sm = ex;
#pragma unroll
        for (int off = 8; off > 0; off >>= 1)
            sm += __shfl_xor_sync(0xffffffffu, sm, off);
        float w = ex / sm;
        if (lane == 15) w += 10.0f;
        float z = (lane < 16) ? (w + s_g[t][lane]) : -1e30f;
        float bz = z; int bi = lane;
#pragma unroll
        for (int off = 8; off > 0; off >>= 1) {
            float oz = __shfl_xor_sync(0xffffffffu, bz, off);
            int   oi = __shfl_xor_sync(0xffffffffu, bi, off);
            if (oz > bz || (oz == bz && oi < bi)) { bz = oz; bi = oi; }
        }
        bi = __shfl_sync(0xffffffffu, bi, 0);
        int k = (bi < SLOTS && s_mask[t] != 0.f) ? bi : -1;

        if (warp == 0 && lane < 16)
            out_log[((size_t)b * NSTEP + t) * SSZ + lane] = (lane == bi) ? 1.f : 0.f;

        if (k >= 0) {
            s_tmp[tid] = states[((size_t)b * NSTEP + t) * MSZ + tid];
            if (tid == 0) s_lastwrite[k] = t;
            __syncthreads();
            float acc = 0.f;
            const float4* w4  = (const float4*)(attn_W + (size_t)tid * 1536 + 1024);
            const float4* st4 = (const float4*)s_tmp;
            for (int kk = 0; kk < MSZ / 4; kk++) {
                float4 ww = w4[kk]; float4 s = st4[kk];
                acc += ww.x * s.x + ww.y * s.y + ww.z * s.z + ww.w * s.w;
            }
            s_row[tid] = acc;
            __syncthreads();
            if (warp == k) {
#pragma unroll
                for (int i = 0; i < 16; i++) mp[i] = s_row[lane + 32 * i];
            }
        }

        if (t + 1 < NSTEP) s_q[1 - cur][tid] = qn + gadd;
        __syncthreads();
    }

    for (int s = 0; s < SLOTS; s++) {
        int lw = s_lastwrite[s];
        const float* src = (lw >= 0)
            ? (states + ((size_t)b * NSTEP + lw) * MSZ)
            : (his_mem + ((size_t)b * SLOTS + s) * MSZ);
        out_hm[((size_t)b * SLOTS + s) * MSZ + tid] = src[tid];
    }
}

// ---------------------------------------------------------------------------
extern "C" void kernel_launch(void* const* d_in, const int* in_sizes, int n_in,
                              void* d_out, int out_size)
{
    const float* his_mem     = (const float*)d_in[0];
    const float* states      = (const float*)d_in[1];
    const float* states_mask = (const float*)d_in[2];
    const float* gt          = (const float*)d_in[3];
    const float* gumbel_u    = (const float*)d_in[5];
    const float* attn_W      = (const float*)d_in[6];
    const float* attn_b      = (const float*)d_in[7];
    const float* v           = (const float*)d_in[8];

    float* out     = (float*)d_out;
    float* out_hm  = out;
    float* out_log = out + (size_t)BATCH * SLOTS * MSZ;

    float *qproj = nullptr, *gproj = nullptr, *memproj = nullptr;
    cudaGetSymbolAddress((void**)&qproj, g_qproj);
    cudaGetSymbolAddress((void**)&gproj, g_gproj);
    cudaGetSymbolAddress((void**)&memproj, g_memproj);

    // max L1 carveout toward shared so 2 x 55KB CTAs fit per SM
    cudaFuncSetAttribute(tf32_gemm_all,
                         cudaFuncAttributePreferredSharedMemoryCarveout, 100);

    dim3 grid(MSZ / 128, 512 + 4 + 60);
    tf32_gemm_all<<<grid, 256>>>(states, gt, his_mem, attn_W, attn_b,
                                 qproj, gproj, memproj);

    writer_kernel<<<BATCH, 512>>>(his_mem, states, states_mask, gumbel_u,
                                  attn_W, v, qproj, gproj, memproj,
                                  out_hm, out_log);
}

// round 13
// speedup vs baseline: 2.0629x; 1.0942x over previous
#include <cuda_runtime.h>
#include <math.h>
#include <stdint.h>

#define BATCH 256
#define NSTEP 128
#define MSZ   512
#define SLOTS 15
#define SSZ   16
#define C2TANH 2.88539008177793f   // 2*log2(e); tanh(x)=1-2/(2^(C2*x)+1)

__device__ float g_qproj[(size_t)BATCH * NSTEP * MSZ];   // scaled by C2TANH
__device__ float g_gproj[BATCH * MSZ];                   // scaled by C2TANH
__device__ float g_memproj[BATCH * SLOTS * MSZ];         // scaled by C2TANH

// ---------------------------------------------------------------------------
__device__ __forceinline__ float f2tf(float x) {
    uint32_t r;
    asm("cvt.rna.tf32.f32 %0, %1;" : "=r"(r) : "f"(x));
    return __uint_as_float(r);
}
__device__ __forceinline__ void mma_tf32(float c[4],
                                         uint32_t a0, uint32_t a1,
                                         uint32_t a2, uint32_t a3,
                                         uint32_t b0, uint32_t b1) {
    asm volatile(
        "mma.sync.aligned.m16n8k8.row.col.f32.tf32.tf32.f32 "
        "{%0,%1,%2,%3}, {%4,%5,%6,%7}, {%8,%9}, {%0,%1,%2,%3};"
        : "+f"(c[0]), "+f"(c[1]), "+f"(c[2]), "+f"(c[3])
        : "r"(a0), "r"(a1), "r"(a2), "r"(a3), "r"(b0), "r"(b1));
}

// ---------------------------------------------------------------------------
// Split-TF32 GEMM (proven 401us config: BM=BN=128, BK=32, 256 thr).
// Epilogue scales by C2TANH. grid (4, 288): y<256 qproj, y<258 gproj(+bias),
// else memproj.
// ---------------------------------------------------------------------------
#define BK 32
#define ASTR 72

__global__ __launch_bounds__(256) void tf32_gemm_all(
    const float* __restrict__ states, const float* __restrict__ gt,
    const float* __restrict__ his_mem, const float* __restrict__ W,
    const float* __restrict__ bias, float* __restrict__ qproj,
    float* __restrict__ gproj, float* __restrict__ memproj)
{
    __shared__ float sA[128 * ASTR];
    __shared__ float sB[128 * ASTR];

    int y = blockIdx.y;
    const float *X, *Wb, *addp = nullptr;
    float* outp;
    int r0;
    if (y < 256)      { X = states;  r0 = y * 128;         Wb = W;        outp = qproj; }
    else if (y < 258) { X = gt;      r0 = (y - 256) * 128; Wb = W + 512;  outp = gproj; addp = bias; }
    else              { X = his_mem; r0 = (y - 258) * 128; Wb = W + 1024; outp = memproj; }

    int tid  = threadIdx.x;
    int warp = tid >> 5, lane = tid & 31;
    int g    = lane >> 2, tig = lane & 3;
    int wm   = (warp >> 2) * 64;
    int wn   = (warp & 3) * 32;
    int n0   = blockIdx.x * 128;

    float acc[4][4][4];
#pragma unroll
    for (int a = 0; a < 4; a++)
#pragma unroll
        for (int b = 0; b < 4; b++)
#pragma unroll
            for (int c = 0; c < 4; c++) acc[a][b][c] = 0.f;

    int lr = tid >> 3;
    int kq = tid & 7;

    float4 pa[4], pb[4];
#pragma unroll
    for (int i = 0; i < 4; i++) {
        pa[i] = *(const float4*)&X[(size_t)(r0 + lr + 32 * i) * 512 + kq * 4];
        pb[i] = *(const float4*)&Wb[(size_t)(n0 + lr + 32 * i) * 1536 + kq * 4];
    }

    for (int t = 0; t < 512 / BK; t++) {
        __syncthreads();
#pragma unroll
        for (int i = 0; i < 4; i++) {
            float4 v = pa[i];
            float h0 = f2tf(v.x), h1 = f2tf(v.y), h2 = f2tf(v.z), h3 = f2tf(v.w);
            float4 s0 = {h0, f2tf(v.x - h0), h1, f2tf(v.y - h1)};
            float4 s1 = {h2, f2tf(v.z - h2), h3, f2tf(v.w - h3)};
            float* dst = &sA[(lr + 32 * i) * ASTR + kq * 8];
            *(float4*)dst = s0; *(float4*)(dst + 4) = s1;

            v = pb[i];
            h0 = f2tf(v.x); h1 = f2tf(v.y); h2 = f2tf(v.z); h3 = f2tf(v.w);
            float4 t0 = {h0, f2tf(v.x - h0), h1, f2tf(v.y - h1)};
            float4 t1 = {h2, f2tf(v.z - h2), h3, f2tf(v.w - h3)};
            dst = &sB[(lr + 32 * i) * ASTR + kq * 8];
            *(float4*)dst = t0; *(float4*)(dst + 4) = t1;
        }
        __syncthreads();

        if (t + 1 < 512 / BK) {
            int k0 = (t + 1) * BK;
#pragma unroll
            for (int i = 0; i < 4; i++) {
                pa[i] = *(const float4*)&X[(size_t)(r0 + lr + 32 * i) * 512 + k0 + kq * 4];
                pb[i] = *(const float4*)&Wb[(size_t)(n0 + lr + 32 * i) * 1536 + k0 + kq * 4];
            }
        }

#pragma unroll
        for (int k8 = 0; k8 < BK / 8; k8++) {
            uint32_t Ah[4][4], Al[4][4], Bh[4][2], Bl[4][2];
#pragma unroll
            for (int mf = 0; mf < 4; mf++) {
                int m0 = wm + mf * 16;
                float2 v0 = *(float2*)&sA[(m0 + g)     * ASTR + (k8 * 8 + tig)     * 2];
                float2 v1 = *(float2*)&sA[(m0 + g + 8) * ASTR + (k8 * 8 + tig)     * 2];
                float2 v2 = *(float2*)&sA[(m0 + g)     * ASTR + (k8 * 8 + tig + 4) * 2];
                float2 v3 = *(float2*)&sA[(m0 + g + 8) * ASTR + (k8 * 8 + tig + 4) * 2];
                Ah[mf][0] = __float_as_uint(v0.x); Al[mf][0] = __float_as_uint(v0.y);
                Ah[mf][1] = __float_as_uint(v1.x); Al[mf][1] = __float_as_uint(v1.y);
                Ah[mf][2] = __float_as_uint(v2.x); Al[mf][2] = __float_as_uint(v2.y);
                Ah[mf][3] = __float_as_uint(v3.x); Al[mf][3] = __float_as_uint(v3.y);
            }
#pragma unroll
            for (int nf = 0; nf < 4; nf++) {
                int n = wn + nf * 8 + g;
                float2 v0 = *(float2*)&sB[n * ASTR + (k8 * 8 + tig)     * 2];
                float2 v1 = *(float2*)&sB[n * ASTR + (k8 * 8 + tig + 4) * 2];
                Bh[nf][0] = __float_as_uint(v0.x); Bl[nf][0] = __float_as_uint(v0.y);
                Bh[nf][1] = __float_as_uint(v1.x); Bl[nf][1] = __float_as_uint(v1.y);
            }
#pragma unroll
            for (int mf = 0; mf < 4; mf++)
#pragma unroll
                for (int nf = 0; nf < 4; nf++) {
                    mma_tf32(acc[mf][nf], Ah[mf][0], Ah[mf][1], Ah[mf][2], Ah[mf][3],
                             Bh[nf][0], Bh[nf][1]);
                    mma_tf32(acc[mf][nf], Ah[mf][0], Ah[mf][1], Ah[mf][2], Ah[mf][3],
                             Bl[nf][0], Bl[nf][1]);
                    mma_tf32(acc[mf][nf], Al[mf][0], Al[mf][1], Al[mf][2], Al[mf][3],
                             Bh[nf][0], Bh[nf][1]);
                }
        }
    }

#pragma unroll
    for (int mf = 0; mf < 4; mf++)
#pragma unroll
        for (int nf = 0; nf < 4; nf++) {
            int col_l = wn + nf * 8 + 2 * tig;
            int col   = n0 + col_l;
            int row   = r0 + wm + mf * 16 + g;
            float a0 = 0.f, a1 = 0.f;
            if (addp) { a0 = addp[col]; a1 = addp[col + 1]; }
            float2 s0 = {(acc[mf][nf][0] + a0) * C2TANH, (acc[mf][nf][1] + a1) * C2TANH};
            float2 s1 = {(acc[mf][nf][2] + a0) * C2TANH, (acc[mf][nf][3] + a1) * C2TANH};
            *(float2*)&outp[(size_t)row * MSZ + col]       = s0;
            *(float2*)&outp[(size_t)(row + 8) * MSZ + col] = s1;
        }
}

// ---------------------------------------------------------------------------
__device__ __forceinline__ float sig2r(float x) {   // rcp(2^x + 1)
    float e;
    asm("ex2.approx.f32 %0, %1;" : "=f"(e) : "f"(x));
    float r;
    asm("rcp.approx.f32 %0, %1;" : "=f"(r) : "f"(e + 1.0f));
    return r;
}

__device__ __forceinline__ int decide(float e, float gn, int lane) {
    float mx = e;
#pragma unroll
    for (int off = 8; off > 0; off >>= 1)
        mx = fmaxf(mx, __shfl_xor_sync(0xffffffffu, mx, off));
    float ex = expf(e - mx);
    float sm = ex;
#pragma unroll
    for (int off = 8; off > 0; off >>= 1)
        sm += __shfl_xor_sync(0xffffffffu, sm, off);
    float w = ex / sm;
    if (lane == 15) w += 10.0f;
    float z = (lane < 16) ? (w + gn) : -1e30f;
    float bz = z; int bi = lane;
#pragma unroll
    for (int off = 8; off > 0; off >>= 1) {
        float oz = __shfl_xor_sync(0xffffffffu, bz, off);
        int   oi = __shfl_xor_sync(0xffffffffu, bi, off);
        if (oz > bz || (oz == bz && oi < bi)) { bz = oz; bi = oi; }
    }
    return __shfl_sync(0xffffffffu, bi, 0);
}

// ---------------------------------------------------------------------------
// writer4: tiled-E0 (smem-staged, 1x global traffic) + parallel decide +
// rare replay from first event. energy e = Vsum - 2*sum(v*rcp(2^x+1)),
// x = scaled (q+g+mem) projections.
// ---------------------------------------------------------------------------
__global__ __launch_bounds__(512, 2) void writer4(
    const float* __restrict__ his_mem, const float* __restrict__ states,
    const float* __restrict__ states_mask, const float* __restrict__ gumbel_u,
    const float* __restrict__ attn_W, const float* __restrict__ v,
    const float* __restrict__ qproj, const float* __restrict__ gproj,
    const float* __restrict__ memproj,
    float* __restrict__ out_hm, float* __restrict__ out_log)
{
    __shared__ float s_E0[NSTEP][SSZ];
    __shared__ float s_g[NSTEP][SSZ];
    __shared__ float s_qt[8 * MSZ];       // E0 tile buffer; replay: [0:512)=q, [512:1024)=state
    __shared__ float s_v[MSZ];
    __shared__ float s_row[MSZ];
    __shared__ float s_mask[NSTEP];
    __shared__ int   s_dec[NSTEP];
    __shared__ float s_e[SSZ];
    __shared__ int   s_dirty[SSZ];
    __shared__ int   s_lastwrite[SLOTS];
    __shared__ int   s_t0;

    int b = blockIdx.x, tid = threadIdx.x, lane = tid & 31, warp = tid >> 5;

    if (tid < SLOTS) s_lastwrite[tid] = -1;
    if (tid < SSZ)   s_dirty[tid] = 0;
    if (tid == 0)    s_t0 = NSTEP;
    if (tid < NSTEP) s_mask[tid] = states_mask[b * NSTEP + tid];
    s_v[tid] = v[tid];
    {
        float4 u4 = *(const float4*)(gumbel_u + (size_t)b * NSTEP * SSZ + tid * 4);
        float uu[4] = {u4.x, u4.y, u4.z, u4.w}, gg[4];
#pragma unroll
        for (int i = 0; i < 4; i++) {
            float u = fminf(fmaxf(uu[i], 1e-20f), 1.0f);
            gg[i] = -logf(-logf(u) + 1e-20f);
        }
        *(float4*)(&s_g[0][0] + tid * 4) = make_float4(gg[0], gg[1], gg[2], gg[3]);
    }

    float mp[16];
#pragma unroll
    for (int i = 0; i < 16; i++)
        mp[i] = (warp < SLOTS)
              ? memproj[((size_t)b * SLOTS + warp) * MSZ + lane + 32 * i] : 0.f;

    float ga_t = gproj[b * MSZ + tid];                       // scaled
    const float4* gp4 = (const float4*)(gproj + (size_t)b * MSZ);
    float4 ga4 = gp4[tid & 127];
    __syncthreads();

    float Vsum;
    {
        float vs = 0.f;
#pragma unroll
        for (int i = 0; i < 16; i++) vs += s_v[lane + 32 * i];
#pragma unroll
        for (int off = 16; off > 0; off >>= 1)
            vs += __shfl_xor_sync(0xffffffffu, vs, off);
        Vsum = vs;
    }

    // ---- E0 phase: 16 tiles of 8 steps ----
    const float4* q4 = (const float4*)(qproj + (size_t)b * NSTEP * MSZ);
    float4* s_qt4 = (float4*)s_qt;
    for (int tile = 0; tile < 16; tile++) {
        int tb = tile * 8;
        float4 x0 = q4[(size_t)tb * 128 + tid];
        float4 x1 = q4[(size_t)tb * 128 + tid + 512];
        __syncthreads();   // protect prior tile reads
        x0.x += ga4.x; x0.y += ga4.y; x0.z += ga4.z; x0.w += ga4.w;
        x1.x += ga4.x; x1.y += ga4.y; x1.z += ga4.z; x1.w += ga4.w;
        s_qt4[tid] = x0; s_qt4[tid + 512] = x1;
        __syncthreads();
#pragma unroll
        for (int j = 0; j < 8; j++) {
            float acc = 0.f;
#pragma unroll
            for (int i = 0; i < 16; i++) {
                int m = lane + 32 * i;
                acc += s_v[m] * sig2r(s_qt[j * MSZ + m] + mp[i]);
            }
#pragma unroll
            for (int off = 16; off > 0; off >>= 1)
                acc += __shfl_xor_sync(0xffffffffu, acc, off);
            if (lane == 0) s_E0[tb + j][warp] = fmaf(-2.f, acc, Vsum);
        }
    }
    __syncthreads();

    // ---- decide phase: warp w -> steps 8w..8w+7 ----
    for (int j = 0; j < 8; j++) {
        int t = warp * 8 + j;
        float e = (lane < 16) ? s_E0[t][lane] : -1e30f;
        int bi = decide(e, (lane < 16) ? s_g[t][lane] : 0.f, lane);
        if (lane == 0) {
            s_dec[t] = bi;
            if (bi < SLOTS && s_mask[t] != 0.f) atomicMin(&s_t0, t);
        }
    }
    __syncthreads();

    int t0 = s_t0;
    int tmax = (t0 < NSTEP) ? t0 : NSTEP - 1;
    for (int idx = tid; idx < (tmax + 1) * SSZ; idx += 512) {
        int t = idx >> 4, s = idx & 15;
        out_log[((size_t)b * NSTEP + t) * SSZ + s] = (s == s_dec[t]) ? 1.f : 0.f;
    }

    // ---- rare replay from t0 ----
    if (t0 < NSTEP) {
        float* s_q  = s_qt;
        float* s_st = s_qt + MSZ;
        int k = s_dec[t0];
        for (int t = t0; t < NSTEP; t++) {
            if (k >= 0) {
                s_st[tid] = states[((size_t)b * NSTEP + t) * MSZ + tid];
                if (tid == 0) { s_lastwrite[k] = t; s_dirty[k] = 1; }
                __syncthreads();
                float acc = 0.f;
                const float4* w4  = (const float4*)(attn_W + (size_t)tid * 1536 + 1024);
                const float4* st4 = (const float4*)s_st;
                for (int kk = 0; kk < MSZ / 4; kk++) {
                    float4 ww = w4[kk]; float4 s2 = st4[kk];
                    acc += ww.x * s2.x + ww.y * s2.y + ww.z * s2.z + ww.w * s2.w;
                }
                s_row[tid] = acc * C2TANH;
                __syncthreads();
                if (warp == k) {
#pragma unroll
                    for (int i = 0; i < 16; i++) mp[i] = s_row[lane + 32 * i];
                }
            }
            if (t + 1 >= NSTEP) break;

            int tn = t + 1;
            s_q[tid] = qproj[((size_t)b * NSTEP + tn) * MSZ + tid] + ga_t;
            __syncthreads();
            if (s_dirty[warp]) {
                float acc = 0.f;
#pragma unroll
                for (int i = 0; i < 16; i++) {
                    int m = lane + 32 * i;
                    acc += s_v[m] * sig2r(s_q[m] + mp[i]);
                }
#pragma unroll
                for (int off = 16; off > 0; off >>= 1)
                    acc += __shfl_xor_sync(0xffffffffu, acc, off);
                if (lane == 0) s_e[warp] = fmaf(-2.f, acc, Vsum);
            }
            __syncthreads();

            float e = (lane < 16)
                    ? (s_dirty[lane] ? s_e[lane] : s_E0[tn][lane]) : -1e30f;
            int bi = decide(e, (lane < 16) ? s_g[tn][lane] : 0.f, lane);
            if (warp == 0 && lane < 16)
                out_log[((size_t)b * NSTEP + tn) * SSZ + lane] = (lane == bi) ? 1.f : 0.f;
            k = (bi < SLOTS && s_mask[tn] != 0.f) ? bi : -1;
            __syncthreads();
        }
        __syncthreads();
    }

    for (int s = 0; s < SLOTS; s++) {
        int lw = s_lastwrite[s];
        const float* src = (lw >= 0)
            ? (states + ((size_t)b * NSTEP + lw) * MSZ)
            : (his_mem + ((size_t)b * SLOTS + s) * MSZ);
        out_hm[((size_t)b * SLOTS + s) * MSZ + tid] = src[tid];
    }
}

// ---------------------------------------------------------------------------
extern "C" void kernel_launch(void* const* d_in, const int* in_sizes, int n_in,
                              void* d_out, int out_size)
{
    const float* his_mem     = (const float*)d_in[0];
    const float* states      = (const float*)d_in[1];
    const float* states_mask = (const float*)d_in[2];
    const float* gt          = (const float*)d_in[3];
    const float* gumbel_u    = (const float*)d_in[5];
    const float* attn_W      = (const float*)d_in[6];
    const float* attn_b      = (const float*)d_in[7];
    const float* v           = (const float*)d_in[8];

    float* out     = (float*)d_out;
    float* out_hm  = out;
    float* out_log = out + (size_t)BATCH * SLOTS * MSZ;

    float *qproj = nullptr, *gproj = nullptr, *memproj = nullptr;
    cudaGetSymbolAddress((void**)&qproj, g_qproj);
    cudaGetSymbolAddress((void**)&gproj, g_gproj);
    cudaGetSymbolAddress((void**)&memproj, g_memproj);

    dim3 grid(MSZ / 128, 256 + 2 + 30);
    tf32_gemm_all<<<grid, 256>>>(states, gt, his_mem, attn_W, attn_b,
                                 qproj, gproj, memproj);

    writer4<<<BATCH, 512>>>(his_mem, states, states_mask, gumbel_u,
                            attn_W, v, qproj, gproj, memproj,
                            out_hm, out_log);
}